// round 1
// baseline (speedup 1.0000x reference)
#include <cuda_runtime.h>

#define Bx 4
#define Nn 2048
#define Dd 512
#define Hh 8
#define Ss 2049   // 1 + N
#define NCHUNK 32 // z partial chunks (64 node rows each)

// ---------------- device scratch (no allocations allowed) ----------------
__device__ float g_q0[Dd];                 // Wq @ class_token + bq
__device__ float g_u[Hh][Dd];              // u_h = Wk_h^T q0_h
__device__ float g_ch[Hh];                 // c_h = q0_h . bk_h
__device__ float g_sc[Bx][Hh][Ss];         // scores -> probs (in place)
__device__ float g_zp[NCHUNK][Bx][Hh][Dd]; // z partials
__device__ float g_z[Bx][Hh][Dd];          // z = sum_j p_j x_j

// ---------------- kernel 1: q0 = Wq @ c + bq ----------------
__global__ void k_q0(const float* __restrict__ Wq, const float* __restrict__ bq,
                     const float* __restrict__ ct) {
    __shared__ float c[Dd];
    int t = threadIdx.x;
    c[t] = ct[t];
    __syncthreads();
    const float* row = Wq + (size_t)t * Dd;
    float acc = bq[t];
    #pragma unroll 8
    for (int d = 0; d < Dd; d++) acc += row[d] * c[d];
    g_q0[t] = acc;
}

// ---------------- kernel 2: u_h, c_h ----------------
__global__ void k_u(const float* __restrict__ Wk, const float* __restrict__ bk) {
    int h = blockIdx.x, t = threadIdx.x;
    __shared__ float qh[64];
    if (t < 64) qh[t] = g_q0[h * 64 + t];
    __syncthreads();
    float acc = 0.f;
    #pragma unroll 8
    for (int i = 0; i < 64; i++)
        acc += qh[i] * Wk[(size_t)(h * 64 + i) * Dd + t];
    g_u[h][t] = acc;
    if (t == 0) {
        float c = 0.f;
        for (int i = 0; i < 64; i++) c += qh[i] * bk[h * 64 + i];
        g_ch[h] = c;
    }
}

// ---------------- kernel 3: scores[b,h,j] = (u_h . x_j + c_h)/8, masked ----------------
__global__ void k_scores(const float* __restrict__ nf, const float* __restrict__ ct,
                         const float* __restrict__ masks) {
    const int b = blockIdx.y;
    const int j0 = blockIdx.x * 16;
    __shared__ float xs[16][Dd];
    const int tid = threadIdx.x;
    // cooperative coalesced tile load (class token at j==0)
    for (int idx = tid; idx < 16 * Dd; idx += 256) {
        int r = idx >> 9, d = idx & 511;
        int j = j0 + r;
        float v = 0.f;
        if (j < Ss) v = (j == 0) ? ct[d] : nf[((size_t)b * Nn + (j - 1)) * Dd + d];
        xs[r][d] = v;
    }
    __syncthreads();
    const int w = tid >> 5, lane = tid & 31;   // warp w == head w
    const float* u = g_u[w];
    const float ch = g_ch[w];
    for (int r = 0; r < 16; r++) {
        int j = j0 + r;
        if (j >= Ss) break;
        float s = 0.f;
        #pragma unroll
        for (int d = lane; d < Dd; d += 32) s += u[d] * xs[r][d];
        #pragma unroll
        for (int o = 16; o; o >>= 1) s += __shfl_xor_sync(0xffffffffu, s, o);
        if (lane == 0) {
            float sc = (s + ch) * 0.125f;  // 1/sqrt(64)
            if (j >= 1) {
                float mv = masks[(size_t)b * Nn + (j - 1)];
                if (mv * mv == 0.f) sc = -1e9f;
            }
            g_sc[b][w][j] = sc;
        }
    }
}

// ---------------- kernel 4: softmax over j per (b,h), in place ----------------
__global__ void k_softmax() {
    const int b = blockIdx.x >> 3, h = blockIdx.x & 7;
    __shared__ float s[Ss];
    __shared__ float red[256];
    const int t = threadIdx.x;
    float mx = -1e30f;
    for (int j = t; j < Ss; j += 256) { float v = g_sc[b][h][j]; s[j] = v; mx = fmaxf(mx, v); }
    red[t] = mx; __syncthreads();
    for (int o = 128; o; o >>= 1) { if (t < o) red[t] = fmaxf(red[t], red[t + o]); __syncthreads(); }
    mx = red[0]; __syncthreads();
    float sum = 0.f;
    for (int j = t; j < Ss; j += 256) { float e = expf(s[j] - mx); s[j] = e; sum += e; }
    red[t] = sum; __syncthreads();
    for (int o = 128; o; o >>= 1) { if (t < o) red[t] += red[t + o]; __syncthreads(); }
    float inv = 1.f / red[0];
    for (int j = t; j < Ss; j += 256) g_sc[b][h][j] = s[j] * inv;
}

// ---------------- kernel 5: z partials over 64-row node chunks ----------------
__global__ void k_zpart(const float* __restrict__ nf, const float* __restrict__ ct) {
    const int b = blockIdx.y, c = blockIdx.x; // chunk 0..31 over node rows
    const int t = threadIdx.x;                // t == dim d
    __shared__ float ps[8][64];
    { int h = t >> 6, jj = t & 63;
      ps[h][jj] = g_sc[b][h][1 + c * 64 + jj]; }
    __syncthreads();
    float acc[8];
    #pragma unroll
    for (int h = 0; h < 8; h++) acc[h] = 0.f;
    const float* xp = nf + ((size_t)b * Nn + c * 64) * Dd + t;
    #pragma unroll 4
    for (int jj = 0; jj < 64; jj++) {
        float xv = xp[(size_t)jj * Dd];
        #pragma unroll
        for (int h = 0; h < 8; h++) acc[h] += ps[h][jj] * xv;
    }
    if (c == 0) {  // class-token column (j == 0)
        float cv = ct[t];
        #pragma unroll
        for (int h = 0; h < 8; h++) acc[h] += g_sc[b][h][0] * cv;
    }
    #pragma unroll
    for (int h = 0; h < 8; h++) g_zp[c][b][h][t] = acc[h];
}

// ---------------- kernel 6: reduce z partials (deterministic, no atomics) ----------------
__global__ void k_zred() {
    const int b = blockIdx.x >> 3, h = blockIdx.x & 7;
    const int d = threadIdx.x;
    float s = 0.f;
    #pragma unroll 8
    for (int c = 0; c < NCHUNK; c++) s += g_zp[c][b][h][d];
    g_z[b][h][d] = s;
}

// ---------------- kernel 7: Wv, Wo, residual, LayerNorm, CLS-row output ----------------
__global__ void k_final(const float* __restrict__ Wv, const float* __restrict__ bv,
                        const float* __restrict__ Wo, const float* __restrict__ bo,
                        const float* __restrict__ ct, const float* __restrict__ gamma,
                        const float* __restrict__ beta, float* __restrict__ out) {
    const int b = blockIdx.x, t = threadIdx.x;
    __shared__ float zs[Hh * Dd];
    __shared__ float ws[Dd];
    __shared__ float red[Dd];
    const float* gz = &g_z[0][0][0];
    for (int idx = t; idx < Hh * Dd; idx += Dd) zs[idx] = gz[(size_t)b * Hh * Dd + idx];
    __syncthreads();
    {   // w_i = bv_i + Wv_i . z[b, i/64]
        int h = t >> 6;
        const float* wr = Wv + (size_t)t * Dd;
        const float* zr = zs + h * Dd;
        float acc = bv[t];
        #pragma unroll 8
        for (int d = 0; d < Dd; d++) acc += wr[d] * zr[d];
        ws[t] = acc;
    }
    __syncthreads();
    float y;
    {   // out_o = bo_o + Wo_o . w ; residual with x0 = class_token
        const float* wr = Wo + (size_t)t * Dd;
        float acc = bo[t];
        #pragma unroll 8
        for (int i = 0; i < Dd; i++) acc += wr[i] * ws[i];
        y = acc + ct[t];
    }
    // LayerNorm over D=512 (block = 512 threads)
    red[t] = y; __syncthreads();
    for (int o = 256; o; o >>= 1) { if (t < o) red[t] += red[t + o]; __syncthreads(); }
    float mu = red[0] * (1.f / Dd); __syncthreads();
    float dy = y - mu;
    red[t] = dy * dy; __syncthreads();
    for (int o = 256; o; o >>= 1) { if (t < o) red[t] += red[t + o]; __syncthreads(); }
    float var = red[0] * (1.f / Dd);
    out[(size_t)b * Dd + t] = dy * rsqrtf(var + 1e-5f) * gamma[t] + beta[t];
}

// ---------------- launcher ----------------
extern "C" void kernel_launch(void* const* d_in, const int* in_sizes, int n_in,
                              void* d_out, int out_size) {
    const float* nf    = (const float*)d_in[0];   // node_feat [B,N,D]
    // d_in[1] edge_weights, d_in[2] adj_matrix: provably unused for CLS-row output
    const float* masks = (const float*)d_in[3];   // [B,N]
    const float* ct    = (const float*)d_in[4];   // class_token [D]
    const float* Wq    = (const float*)d_in[5];
    const float* bq    = (const float*)d_in[6];
    const float* Wk    = (const float*)d_in[7];
    const float* bk    = (const float*)d_in[8];
    const float* Wv    = (const float*)d_in[9];
    const float* bv    = (const float*)d_in[10];
    const float* Wo    = (const float*)d_in[11];
    const float* bo    = (const float*)d_in[12];
    const float* gamma = (const float*)d_in[13];
    const float* beta  = (const float*)d_in[14];
    float* out = (float*)d_out;

    k_q0<<<1, Dd>>>(Wq, bq, ct);
    k_u<<<Hh, Dd>>>(Wk, bk);
    k_scores<<<dim3((Ss + 15) / 16, Bx), 256>>>(nf, ct, masks);
    k_softmax<<<Bx * Hh, 256>>>();
    k_zpart<<<dim3(NCHUNK, Bx), Dd>>>(nf, ct);
    k_zred<<<Bx * Hh, Dd>>>();
    k_final<<<Bx, Dd>>>(Wv, bv, Wo, bo, ct, gamma, beta, out);
}

// round 2
// speedup vs baseline: 7.7443x; 7.7443x over previous
#include <cuda_runtime.h>

#define Bx 4
#define Nn 2048
#define Dd 512
#define Hh 8
#define NCH 64      // chunks of 32 node rows each
#define ROWS 32     // rows per chunk
#define SUB 16      // rows per subtile

// ---------------- device scratch ----------------
__device__ float g_u[Hh][Dd];              // u_h = Wk_h^T q0_h
__device__ float g_ch[Hh];                 // c_h = q0_h . bk_h
__device__ float g_s0[Hh];                 // cls-token score per head (scaled)
__device__ float g_pm[Bx][NCH][Hh];        // per-chunk running max
__device__ float g_ps[Bx][NCH][Hh];        // per-chunk exp-sum
__device__ float g_zp[NCH][Bx][Hh][Dd];    // per-chunk unnormalized z
__device__ float g_w[Bx][Dd];              // w = Wv z + bv

__device__ __forceinline__ float warp_sum(float v) {
    #pragma unroll
    for (int o = 16; o; o >>= 1) v += __shfl_xor_sync(0xffffffffu, v, o);
    return v;
}
__device__ __forceinline__ float warp_max(float v) {
    #pragma unroll
    for (int o = 16; o; o >>= 1) v = fmaxf(v, __shfl_xor_sync(0xffffffffu, v, o));
    return v;
}

// ============ kernel 1: per-head prep: q0 slice, u_h, c_h, s0_h ============
__global__ void k_prep(const float* __restrict__ Wq, const float* __restrict__ bq,
                       const float* __restrict__ Wk, const float* __restrict__ bk,
                       const float* __restrict__ ct) {
    const int h = blockIdx.x, t = threadIdx.x;
    const int wid = t >> 5, lane = t & 31;
    __shared__ float cts[Dd];
    __shared__ float q0s[64];
    __shared__ float ch_sh;
    __shared__ float red[512];
    cts[t] = ct[t];
    __syncthreads();
    // q0[h*64+i] = Wq row (h*64+i) . ct + bq   (16 warps, 4 rows each)
    for (int i = wid; i < 64; i += 16) {
        const float* row = Wq + (size_t)(h * 64 + i) * Dd;
        float s = 0.f;
        #pragma unroll
        for (int d = lane; d < Dd; d += 32) s += row[d] * cts[d];
        s = warp_sum(s);
        if (lane == 0) q0s[i] = s + bq[h * 64 + i];
    }
    __syncthreads();
    if (wid == 0) {   // c_h = q0_h . bk_h
        float s = 0.f;
        for (int i = lane; i < 64; i += 32) s += q0s[i] * bk[h * 64 + i];
        s = warp_sum(s);
        if (lane == 0) { ch_sh = s; g_ch[h] = s; }
    }
    __syncthreads();
    // u_h[t] = sum_i q0s[i] * Wk[h*64+i][t]
    float acc = 0.f;
    #pragma unroll 8
    for (int i = 0; i < 64; i++) acc += q0s[i] * Wk[(size_t)(h * 64 + i) * Dd + t];
    g_u[h][t] = acc;
    // s0 = (u_h . ct + c_h) / 8
    red[t] = acc * cts[t];
    __syncthreads();
    for (int o = 256; o; o >>= 1) { if (t < o) red[t] += red[t + o]; __syncthreads(); }
    if (t == 0) g_s0[h] = (red[0] + ch_sh) * 0.125f;
}

// ============ kernel 2: fused scores + online softmax + weighted sum ============
// grid (NCH, B), 512 threads. One pass over node_feat.
__global__ void k_main(const float* __restrict__ nf, const float* __restrict__ masks) {
    const int c = blockIdx.x, b = blockIdx.y;
    const int t = threadIdx.x, wid = t >> 5, lane = t & 31;
    __shared__ float xs[SUB][Dd];          // 32 KB tile
    __shared__ float sc[Hh][SUB];
    __shared__ float es[Hh][SUB];
    __shared__ float mh[Hh], sh[Hh], alpha[Hh], chs[Hh];
    if (t < Hh) { mh[t] = -3e38f; sh[t] = 0.f; chs[t] = g_ch[t]; }
    float z[Hh];
    #pragma unroll
    for (int h = 0; h < Hh; h++) z[h] = 0.f;
    const float* ub = &g_u[0][0];

    for (int st = 0; st < ROWS / SUB; st++) {
        __syncthreads();
        const int j0 = c * ROWS + st * SUB;   // node index of first row
        // --- coalesced float4 tile load ---
        {
            const float4* src = (const float4*)(nf + ((size_t)b * Nn + j0) * Dd);
            float4* dst = (float4*)&xs[0][0];
            #pragma unroll
            for (int k = 0; k < 4; k++) dst[t + k * 512] = src[t + k * 512];
        }
        __syncthreads();
        // --- scores: warp w -> head w>>1, rows (w&1)*8 .. +8 ---
        {
            const int h = wid >> 1, r0 = (wid & 1) * 8;
            #pragma unroll
            for (int rr = 0; rr < 8; rr++) {
                const int r = r0 + rr;
                float s = 0.f;
                #pragma unroll
                for (int d = lane; d < Dd; d += 32) s += __ldg(&ub[h * Dd + d]) * xs[r][d];
                s = warp_sum(s);
                if (lane == 0) {
                    float mv = masks[(size_t)b * Nn + j0 + r];
                    float v = (s + chs[h]) * 0.125f;
                    if (mv * mv == 0.f) v = -1e9f;
                    sc[h][r] = v;
                }
            }
        }
        __syncthreads();
        // --- online softmax update per head (warps 0..7) ---
        if (wid < Hh) {
            const int h = wid;
            float v = (lane < SUB) ? sc[h][lane] : -3e38f;
            float m = warp_max(v);
            float mnew = fmaxf(mh[h], m);
            float e = (lane < SUB) ? expf(v - mnew) : 0.f;
            float ss = warp_sum(e);
            if (lane < SUB) es[h][lane] = e;
            if (lane == 0) {
                float a = expf(mh[h] - mnew);
                alpha[h] = a;
                sh[h] = sh[h] * a + ss;
                mh[h] = mnew;
            }
        }
        __syncthreads();
        // --- z accumulation: thread t owns dim d=t ---
        #pragma unroll
        for (int h = 0; h < Hh; h++) z[h] *= alpha[h];
        #pragma unroll 4
        for (int r = 0; r < SUB; r++) {
            const float xv = xs[r][t];
            #pragma unroll
            for (int h = 0; h < Hh; h++) z[h] += es[h][r] * xv;
        }
    }
    // write partials
    #pragma unroll
    for (int h = 0; h < Hh; h++) g_zp[c][b][h][t] = z[h];
    if (t < Hh) { g_pm[b][c][t] = mh[t]; g_ps[b][c][t] = sh[t]; }
}

// ============ kernel 3: per (b,h): combine chunks, add CLS, Wv GEMV ============
// grid (B, H), 256 threads
__global__ void k_wv(const float* __restrict__ ct, const float* __restrict__ Wv,
                     const float* __restrict__ bv) {
    const int b = blockIdx.x, h = blockIdx.y;
    const int t = threadIdx.x, wid = t >> 5, lane = t & 31;
    __shared__ float f[NCH];
    __shared__ float zs[Dd];
    __shared__ float Msh, Ssh, f0sh;
    // M and S over 64 chunk partials + cls score (warp 0)
    if (wid == 0) {
        float pm0 = g_pm[b][lane][h],      pm1 = g_pm[b][lane + 32][h];
        float s0  = g_s0[h];
        float m = warp_max(fmaxf(pm0, pm1));
        m = fmaxf(m, s0);
        float e = g_ps[b][lane][h] * expf(pm0 - m)
                + g_ps[b][lane + 32][h] * expf(pm1 - m);
        e = warp_sum(e);
        if (lane == 0) {
            float S = e + expf(s0 - m);
            Msh = m; Ssh = S; f0sh = expf(s0 - m) / S;
        }
    }
    __syncthreads();
    if (t < NCH) f[t] = expf(g_pm[b][t][h] - Msh) / Ssh;
    __syncthreads();
    // z[d] = f0*ct[d] + sum_c f[c]*zp[c][b][h][d]
    for (int d = t; d < Dd; d += 256) {
        float acc = f0sh * ct[d];
        #pragma unroll 8
        for (int c = 0; c < NCH; c++) acc += f[c] * g_zp[c][b][h][d];
        zs[d] = acc;
    }
    __syncthreads();
    // w[h*64+ii] = bv + Wv row . z   (8 warps x 8 rows)
    for (int ii = wid; ii < 64; ii += 8) {
        const int i = h * 64 + ii;
        const float* row = Wv + (size_t)i * Dd;
        float s = 0.f;
        #pragma unroll
        for (int d = lane; d < Dd; d += 32) s += row[d] * zs[d];
        s = warp_sum(s);
        if (lane == 0) g_w[b][i] = s + bv[i];
    }
}

// ============ kernel 4: y = Wo w + bo + ct, LayerNorm, output CLS row ============
// grid B, 1024 threads
__global__ void k_yln(const float* __restrict__ Wo, const float* __restrict__ bo,
                      const float* __restrict__ ct, const float* __restrict__ gamma,
                      const float* __restrict__ beta, float* __restrict__ out) {
    const int b = blockIdx.x, t = threadIdx.x, wid = t >> 5, lane = t & 31;
    __shared__ float ws[Dd], ys[Dd];
    __shared__ float red[1024];
    if (t < Dd) ws[t] = g_w[b][t];
    __syncthreads();
    // 32 warps x 16 rows
    #pragma unroll 2
    for (int m = 0; m < 16; m++) {
        const int r = wid * 16 + m;
        const float* row = Wo + (size_t)r * Dd;
        float s = 0.f;
        #pragma unroll
        for (int d = lane; d < Dd; d += 32) s += row[d] * ws[d];
        s = warp_sum(s);
        if (lane == 0) ys[r] = s + bo[r] + ct[r];
    }
    __syncthreads();
    // mean
    red[t] = (t < Dd) ? ys[t] : 0.f;
    __syncthreads();
    for (int o = 512; o; o >>= 1) { if (t < o) red[t] += red[t + o]; __syncthreads(); }
    const float mu = red[0] * (1.f / Dd);
    __syncthreads();
    float dy = (t < Dd) ? (ys[t] - mu) : 0.f;
    red[t] = dy * dy;
    __syncthreads();
    for (int o = 512; o; o >>= 1) { if (t < o) red[t] += red[t + o]; __syncthreads(); }
    const float var = red[0] * (1.f / Dd);
    if (t < Dd)
        out[(size_t)b * Dd + t] = dy * rsqrtf(var + 1e-5f) * gamma[t] + beta[t];
}

// ---------------- launcher ----------------
extern "C" void kernel_launch(void* const* d_in, const int* in_sizes, int n_in,
                              void* d_out, int out_size) {
    const float* nf    = (const float*)d_in[0];   // node_feat [B,N,D]
    // d_in[1] edge_weights, d_in[2] adj_matrix: dead for CLS-row output
    const float* masks = (const float*)d_in[3];   // [B,N]
    const float* ct    = (const float*)d_in[4];   // class_token [D]
    const float* Wq    = (const float*)d_in[5];
    const float* bq    = (const float*)d_in[6];
    const float* Wk    = (const float*)d_in[7];
    const float* bk    = (const float*)d_in[8];
    const float* Wv    = (const float*)d_in[9];
    const float* bv    = (const float*)d_in[10];
    const float* Wo    = (const float*)d_in[11];
    const float* bo    = (const float*)d_in[12];
    const float* gamma = (const float*)d_in[13];
    const float* beta  = (const float*)d_in[14];
    float* out = (float*)d_out;

    k_prep<<<Hh, Dd>>>(Wq, bq, Wk, bk, ct);
    k_main<<<dim3(NCH, Bx), Dd>>>(nf, masks);
    k_wv<<<dim3(Bx, Hh), 256>>>(ct, Wv, bv);
    k_yln<<<Bx, 1024>>>(Wo, bo, ct, gamma, beta, out);
}

// round 3
// speedup vs baseline: 12.1457x; 1.5683x over previous
#include <cuda_runtime.h>
#include <cuda_pipeline.h>

#define Bx 4
#define Nn 2048
#define Dd 512
#define Hh 8
#define NCH 64      // chunks of 32 node rows
#define ROWS 32
#define SUB 16
#define NSUB (ROWS / SUB)

// ---------------- device scratch ----------------
__device__ float g_q0[Dd];
__device__ float g_u[Hh][Dd];
__device__ float g_ch[Hh];
__device__ float g_s0p[Hh][8];             // partial u.ct per 64-dim chunk
__device__ float g_pm[Bx][NCH][Hh];
__device__ float g_ps[Bx][NCH][Hh];
__device__ float g_zp[NCH][Bx][Hh][Dd];    // per-chunk unnormalized z
__device__ float g_z2[Bx][Hh][8][Dd];      // f-weighted group sums
__device__ float g_w[Bx][Dd];              // Wv z + bv
__device__ float g_y[Bx][Dd];              // pre-LN y

__device__ __forceinline__ float warp_sum(float v) {
    #pragma unroll
    for (int o = 16; o; o >>= 1) v += __shfl_xor_sync(0xffffffffu, v, o);
    return v;
}
__device__ __forceinline__ float warp_max(float v) {
    #pragma unroll
    for (int o = 16; o; o >>= 1) v = fmaxf(v, __shfl_xor_sync(0xffffffffu, v, o));
    return v;
}
__device__ __forceinline__ float dot4(float4 a, float4 b) {
    return a.x * b.x + a.y * b.y + a.z * b.z + a.w * b.w;
}

// ============ k_q0: q0 = Wq @ ct + bq. grid 64, block 256 ============
__global__ void k_q0(const float* __restrict__ Wq, const float* __restrict__ bq,
                     const float* __restrict__ ct) {
    __shared__ __align__(16) float cts[Dd];
    const int t = threadIdx.x, wid = t >> 5, lane = t & 31;
    cts[t] = ct[t]; cts[t + 256] = ct[t + 256];
    __syncthreads();
    const int r = blockIdx.x * 8 + wid;
    const float4* row = (const float4*)(Wq + (size_t)r * Dd);
    const float4* cv = (const float4*)cts;
    float s = 0.f;
    #pragma unroll
    for (int k = 0; k < 4; k++) s += dot4(row[lane + 32 * k], cv[lane + 32 * k]);
    s = warp_sum(s);
    if (lane == 0) g_q0[r] = s + bq[r];
}

// ============ k_u: u_h = Wk_h^T q0_h (+ s0 partials + ch). grid (8h, 8dc), block 256 ============
__global__ void k_u(const float* __restrict__ Wk, const float* __restrict__ bk,
                    const float* __restrict__ ct) {
    const int h = blockIdx.x, dc = blockIdx.y;
    const int t = threadIdx.x;
    __shared__ float q0s[64], cts[64], red4[4][64], red64[64];
    if (t < 64) { q0s[t] = g_q0[h * 64 + t]; cts[t] = ct[dc * 64 + t]; }
    __syncthreads();
    const int dl = t & 63, part = t >> 6;
    const float* base = Wk + (size_t)(h * 64 + part * 16) * Dd + dc * 64 + dl;
    float acc = 0.f;
    #pragma unroll
    for (int i = 0; i < 16; i++) acc += q0s[part * 16 + i] * base[(size_t)i * Dd];
    red4[part][dl] = acc;
    __syncthreads();
    if (t < 64) {
        float u = red4[0][t] + red4[1][t] + red4[2][t] + red4[3][t];
        g_u[h][dc * 64 + t] = u;
        red64[t] = u * cts[t];
    }
    __syncthreads();
    if (t < 32) {
        float v = red64[t] + red64[t + 32];
        v = warp_sum(v);
        if (t == 0) g_s0p[h][dc] = v;
        if (dc == 0) {   // ch = q0_h . bk_h
            float cvv = q0s[t] * bk[h * 64 + t] + q0s[t + 32] * bk[h * 64 + t + 32];
            cvv = warp_sum(cvv);
            if (t == 0) g_ch[h] = cvv;
        }
    }
}

// ============ k_main: fused scores + online softmax + weighted sum ============
// grid (NCH, B), 512 threads, dyn smem = 2 tile buffers (64 KB)
__global__ void k_main(const float* __restrict__ nf, const float* __restrict__ masks) {
    extern __shared__ __align__(16) float dyn[];
    float* xs[2] = { dyn, dyn + SUB * Dd };
    __shared__ __align__(16) float us[Hh][Dd];   // 16 KB
    __shared__ float sc[Hh][SUB], es[Hh][SUB];
    __shared__ float mh[Hh], sh[Hh], alpha[Hh], chs[Hh], msk[ROWS];
    const int c = blockIdx.x, b = blockIdx.y;
    const int t = threadIdx.x, wid = t >> 5, lane = t & 31;

    if (t < Hh) { mh[t] = -3e38f; sh[t] = 0.f; chs[t] = g_ch[t]; }
    if (t < ROWS) msk[t] = masks[(size_t)b * Nn + c * ROWS + t];
    {
        const float* uf = &g_u[0][0];
        #pragma unroll
        for (int k = 0; k < 8; k++) us[0][t + k * 512] = uf[t + k * 512];
    }
    // issue both tile loads up front (cp.async)
    #pragma unroll
    for (int st = 0; st < NSUB; st++) {
        const float4* src = (const float4*)(nf + ((size_t)b * Nn + c * ROWS + st * SUB) * Dd);
        float4* dst = (float4*)xs[st];
        #pragma unroll
        for (int k = 0; k < 4; k++)
            __pipeline_memcpy_async(&dst[t + k * 512], &src[t + k * 512], 16);
        __pipeline_commit();
    }

    float z[Hh];
    #pragma unroll
    for (int h = 0; h < Hh; h++) z[h] = 0.f;

    #pragma unroll
    for (int st = 0; st < NSUB; st++) {
        __pipeline_wait_prior(NSUB - 1 - st);
        __syncthreads();
        const float* xt = xs[st];
        // scores: warp w -> head w>>1, rows (w&1)*8..+8
        {
            const int h = wid >> 1, r0 = (wid & 1) * 8;
            const float4* uf4 = (const float4*)us[h];
            #pragma unroll
            for (int rr = 0; rr < 8; rr++) {
                const int r = r0 + rr;
                const float4* xf4 = (const float4*)(xt + r * Dd);
                float s = 0.f;
                #pragma unroll
                for (int k = 0; k < 4; k++) s += dot4(uf4[lane + 32 * k], xf4[lane + 32 * k]);
                s = warp_sum(s);
                if (lane == 0) {
                    float mv = msk[st * SUB + r];
                    float v = (s + chs[h]) * 0.125f;
                    if (mv * mv == 0.f) v = -1e9f;
                    sc[h][r] = v;
                }
            }
        }
        __syncthreads();
        if (wid < Hh) {   // online softmax per head
            const int h = wid;
            float v = (lane < SUB) ? sc[h][lane] : -3e38f;
            float m = warp_max(v);
            float mnew = fmaxf(mh[h], m);
            float e = (lane < SUB) ? expf(v - mnew) : 0.f;
            float ss = warp_sum(e);
            if (lane < SUB) es[h][lane] = e;
            if (lane == 0) {
                alpha[h] = expf(mh[h] - mnew);
                sh[h] = sh[h] * alpha[h] + ss;
                mh[h] = mnew;
            }
        }
        __syncthreads();
        #pragma unroll
        for (int h = 0; h < Hh; h++) z[h] *= alpha[h];
        #pragma unroll 4
        for (int r = 0; r < SUB; r++) {
            const float xv = xt[r * Dd + t];
            #pragma unroll
            for (int h = 0; h < Hh; h++) z[h] += es[h][r] * xv;
        }
    }
    __syncthreads();
    #pragma unroll
    for (int h = 0; h < Hh; h++) g_zp[c][b][h][t] = z[h];
    if (t < Hh) { g_pm[b][c][t] = mh[t]; g_ps[b][c][t] = sh[t]; }
}

// ============ k_red: f-weighted reduce of 8 chunks per block. grid (B,H,8), 512 thr ============
__global__ void k_red(const float* __restrict__ ct) {
    const int b = blockIdx.x, h = blockIdx.y, g = blockIdx.z;
    const int t = threadIdx.x, lane = t & 31;
    __shared__ float fsh[8], f0sh;
    if (t < 32) {
        float sp = (lane < 8) ? g_s0p[h][lane] : 0.f;
        sp = warp_sum(sp);
        const float s0 = (sp + g_ch[h]) * 0.125f;
        float pm0 = g_pm[b][lane][h], pm1 = g_pm[b][lane + 32][h];
        float M = fmaxf(warp_max(fmaxf(pm0, pm1)), s0);
        float e = g_ps[b][lane][h] * expf(pm0 - M) + g_ps[b][lane + 32][h] * expf(pm1 - M);
        e = warp_sum(e);
        const float S = e + expf(s0 - M);
        if (lane < 8) fsh[lane] = expf(g_pm[b][g * 8 + lane][h] - M) / S;
        if (lane == 0) f0sh = expf(s0 - M) / S;
    }
    __syncthreads();
    float acc = (g == 0) ? f0sh * ct[t] : 0.f;
    #pragma unroll
    for (int cc = 0; cc < 8; cc++) acc += fsh[cc] * g_zp[g * 8 + cc][b][h][t];
    g_z2[b][h][g][t] = acc;
}

// ============ k_wv: w = Wv z + bv, all batches per block. grid (H, 8), 256 thr ============
__global__ void k_wv(const float* __restrict__ Wv, const float* __restrict__ bv) {
    const int h = blockIdx.x, rg = blockIdx.y;
    const int t = threadIdx.x, wid = t >> 5, lane = t & 31;
    __shared__ __align__(16) float zs[Bx][Dd];
    for (int idx = t; idx < Bx * Dd; idx += 256) {
        const int b = idx >> 9, d = idx & 511;
        float a = 0.f;
        #pragma unroll
        for (int gg = 0; gg < 8; gg++) a += g_z2[b][h][gg][d];
        zs[b][d] = a;
    }
    __syncthreads();
    const int i = h * 64 + rg * 8 + wid;
    const float4* row = (const float4*)(Wv + (size_t)i * Dd);
    float sb[Bx] = {0.f, 0.f, 0.f, 0.f};
    #pragma unroll
    for (int k = 0; k < 4; k++) {
        const float4 rv = row[lane + 32 * k];
        #pragma unroll
        for (int b = 0; b < Bx; b++)
            sb[b] += dot4(rv, ((const float4*)zs[b])[lane + 32 * k]);
    }
    #pragma unroll
    for (int b = 0; b < Bx; b++) {
        sb[b] = warp_sum(sb[b]);
        if (lane == 0) g_w[b][i] = sb[b] + bv[i];
    }
}

// ============ k_wo: y = Wo w + bo + ct, all batches. grid 128, 256 thr ============
__global__ void k_wo(const float* __restrict__ Wo, const float* __restrict__ bo,
                     const float* __restrict__ ct) {
    const int t = threadIdx.x, wid = t >> 5, lane = t & 31;
    __shared__ __align__(16) float ws[Bx][Dd];
    __shared__ float part[4][2][Bx];
    for (int idx = t; idx < Bx * Dd; idx += 256)
        ws[idx >> 9][idx & 511] = g_w[idx >> 9][idx & 511];
    __syncthreads();
    const int rloc = wid >> 1, half = wid & 1;
    const int r = blockIdx.x * 4 + rloc;
    const float4* row = (const float4*)(Wo + (size_t)r * Dd) + half * 64;
    float sb[Bx] = {0.f, 0.f, 0.f, 0.f};
    #pragma unroll
    for (int k = 0; k < 2; k++) {
        const float4 rv = row[lane + 32 * k];
        #pragma unroll
        for (int b = 0; b < Bx; b++)
            sb[b] += dot4(rv, ((const float4*)ws[b])[half * 64 + lane + 32 * k]);
    }
    #pragma unroll
    for (int b = 0; b < Bx; b++) {
        sb[b] = warp_sum(sb[b]);
        if (lane == 0) part[rloc][half][b] = sb[b];
    }
    __syncthreads();
    if (t < 16) {
        const int rl = t >> 2, b = t & 3;
        const int rr = blockIdx.x * 4 + rl;
        g_y[b][rr] = part[rl][0][b] + part[rl][1][b] + bo[rr] + ct[rr];
    }
}

// ============ k_ln: LayerNorm CLS row. grid B, 512 thr ============
__global__ void k_ln(const float* __restrict__ gamma, const float* __restrict__ beta,
                     float* __restrict__ out) {
    const int b = blockIdx.x, t = threadIdx.x;
    __shared__ float red[512];
    const float y = g_y[b][t];
    red[t] = y; __syncthreads();
    for (int o = 256; o; o >>= 1) { if (t < o) red[t] += red[t + o]; __syncthreads(); }
    const float mu = red[0] * (1.f / Dd);
    __syncthreads();
    const float dy = y - mu;
    red[t] = dy * dy; __syncthreads();
    for (int o = 256; o; o >>= 1) { if (t < o) red[t] += red[t + o]; __syncthreads(); }
    const float var = red[0] * (1.f / Dd);
    out[(size_t)b * Dd + t] = dy * rsqrtf(var + 1e-5f) * gamma[t] + beta[t];
}

// ---------------- launcher ----------------
extern "C" void kernel_launch(void* const* d_in, const int* in_sizes, int n_in,
                              void* d_out, int out_size) {
    const float* nf    = (const float*)d_in[0];
    // d_in[1] edge_weights, d_in[2] adj_matrix: dead for CLS-row output
    const float* masks = (const float*)d_in[3];
    const float* ct    = (const float*)d_in[4];
    const float* Wq    = (const float*)d_in[5];
    const float* bq    = (const float*)d_in[6];
    const float* Wk    = (const float*)d_in[7];
    const float* bk    = (const float*)d_in[8];
    const float* Wv    = (const float*)d_in[9];
    const float* bv    = (const float*)d_in[10];
    const float* Wo    = (const float*)d_in[11];
    const float* bo    = (const float*)d_in[12];
    const float* gamma = (const float*)d_in[13];
    const float* beta  = (const float*)d_in[14];
    float* out = (float*)d_out;

    const int dyn = 2 * SUB * Dd * sizeof(float);   // 64 KB
    static bool attr_set = false;
    if (!attr_set) {
        cudaFuncSetAttribute(k_main, cudaFuncAttributeMaxDynamicSharedMemorySize, dyn);
        attr_set = true;
    }

    k_q0  <<<64, 256>>>(Wq, bq, ct);
    k_u   <<<dim3(Hh, 8), 256>>>(Wk, bk, ct);
    k_main<<<dim3(NCH, Bx), 512, dyn>>>(nf, masks);
    k_red <<<dim3(Bx, Hh, 8), 512>>>(ct);
    k_wv  <<<dim3(Hh, 8), 256>>>(Wv, bv);
    k_wo  <<<128, 256>>>(Wo, bo, ct);
    k_ln  <<<Bx, 512>>>(gamma, beta, out);
}